// round 3
// baseline (speedup 1.0000x reference)
#include <cuda_runtime.h>
#include <cuda_fp16.h>
#include <stdint.h>

#define NN 100000
#define EE 1600000
#define DD 64

#define SCAN_BS 1024
#define SCAN_NB ((NN + SCAN_BS - 1) / SCAN_BS)   // 98

// ---------------- device scratch (static; no allocation) ----------------
__device__ int   g_flag64;
__device__ int   g_deg[NN];
__device__ int   g_fill[NN];
__device__ int   g_rowptr[NN + 1];
__device__ int   g_blocksums[128];
__device__ int   g_rows[EE];
__device__ int   g_cols[EE];
__device__ float g_q[NN * DD];
__device__ float g_k[NN * DD];
__device__ float g_scores[EE * 4];
__device__ float g_meanatt[EE];
__device__ float g_w[EE];
__device__ float g_yv[NN * DD];
__device__ float g_stA[NN * DD];
__device__ float g_stB[NN * DD];
__device__ float g_acc[NN * DD];
__device__ __half2 g_yvh[NN * 32];
__device__ __half2 g_stAh[NN * 32];
__device__ __half2 g_stBh[NN * 32];
__device__ unsigned g_hist[256];
__device__ unsigned g_selPrefix;
__device__ unsigned g_selMask;
__device__ int      g_selShift;
__device__ unsigned g_selRank;
__device__ unsigned g_selResult[2];
__device__ unsigned g_cntLE;
__device__ unsigned g_minGt;
__device__ float    g_thr;

// ---------------- dtype detection ----------------
__global__ void k_detect(const int* ei32) {
    int t = threadIdx.x;
    int v = ei32[2 * t + 1];
    int any = __syncthreads_or(v != 0);
    if (t == 0) g_flag64 = (any == 0) ? 1 : 0;
}

__device__ __forceinline__ void load_edge(const void* ei, int e, int& r, int& c) {
    if (g_flag64) {
        const long long* p = (const long long*)ei;
        r = (int)p[e];
        c = (int)p[EE + e];
    } else {
        const int* p = (const int*)ei;
        r = p[e];
        c = p[EE + e];
    }
}

// ---------------- init / CSR build ----------------
__global__ void k_zero_counts() {
    int i = blockIdx.x * blockDim.x + threadIdx.x;
    if (i < NN) { g_deg[i] = 0; g_fill[i] = 0; }
}

__global__ void k_count(const void* ei) {
    int e = blockIdx.x * blockDim.x + threadIdx.x;
    if (e >= EE) return;
    int r, c;
    load_edge(ei, e, r, c);
    atomicAdd(&g_deg[r], 1);
}

__global__ void k_scan1() {
    __shared__ int sh[SCAN_BS];
    int t = threadIdx.x;
    int i = blockIdx.x * SCAN_BS + t;
    int v = (i < NN) ? g_deg[i] : 0;
    sh[t] = v;
    __syncthreads();
    for (int off = 1; off < SCAN_BS; off <<= 1) {
        int x = (t >= off) ? sh[t - off] : 0;
        __syncthreads();
        if (t >= off) sh[t] += x;
        __syncthreads();
    }
    if (i < NN) g_rowptr[i] = sh[t] - v;
    if (t == SCAN_BS - 1) g_blocksums[blockIdx.x] = sh[t];
}

__global__ void k_scan2() {
    __shared__ int sh[128];
    int t = threadIdx.x;
    int v = (t < SCAN_NB) ? g_blocksums[t] : 0;
    sh[t] = v;
    __syncthreads();
    for (int off = 1; off < 128; off <<= 1) {
        int x = (t >= off) ? sh[t - off] : 0;
        __syncthreads();
        if (t >= off) sh[t] += x;
        __syncthreads();
    }
    if (t < SCAN_NB) g_blocksums[t] = sh[t] - v;
    if (t == 0) g_rowptr[NN] = EE;
}

__global__ void k_scan3() {
    int i = blockIdx.x * blockDim.x + threadIdx.x;
    if (i < NN) g_rowptr[i] += g_blocksums[i >> 10];
}

__global__ void k_scatter(const void* ei) {
    int e = blockIdx.x * blockDim.x + threadIdx.x;
    if (e >= EE) return;
    int r, c;
    load_edge(ei, e, r, c);
    int pos = g_rowptr[r] + atomicAdd(&g_fill[r], 1);
    g_rows[pos] = r;
    g_cols[pos] = c;
}

// ---------------- q/k GEMM ----------------
__global__ __launch_bounds__(256) void k_gemm(const float* __restrict__ x,
                                              const float* __restrict__ Wq,
                                              const float* __restrict__ Wk) {
    __shared__ float sWq[64 * 64];
    __shared__ float sWk[64 * 64];
    __shared__ float sX[4 * 64];
    int tid = threadIdx.x;
    for (int i = tid; i < 4096; i += 256) { sWq[i] = Wq[i]; sWk[i] = Wk[i]; }
    int rbase = blockIdx.x * 4;
    sX[tid] = x[rbase * 64 + tid];
    __syncthreads();
    int r = tid >> 6;
    int c = tid & 63;
    float aq = 0.f, ak = 0.f;
    #pragma unroll
    for (int t = 0; t < 64; t++) {
        float xv = sX[r * 64 + t];
        aq += xv * sWq[t * 64 + c];
        ak += xv * sWk[t * 64 + c];
    }
    g_q[(rbase + r) * 64 + c] = aq;
    g_k[(rbase + r) * 64 + c] = ak;
}

// ---------------- per-edge scores ----------------
__global__ void k_scores() {
    int e = blockIdx.x * blockDim.x + threadIdx.x;
    if (e >= EE) return;
    int r = g_rows[e], c = g_cols[e];
    const float4* qa = (const float4*)(g_q + (size_t)r * 64);
    const float4* kb = (const float4*)(g_k + (size_t)c * 64);
    float out[4];
    #pragma unroll
    for (int h = 0; h < 4; h++) {
        float acc = 0.f;
        #pragma unroll
        for (int t = 0; t < 4; t++) {
            float4 a = qa[h * 4 + t];
            float4 b = kb[h * 4 + t];
            acc += a.x * b.x + a.y * b.y + a.z * b.z + a.w * b.w;
        }
        out[h] = acc * 0.25f;
    }
    ((float4*)g_scores)[e] = make_float4(out[0], out[1], out[2], out[3]);
}

__device__ __forceinline__ float warp_max(float v) {
    #pragma unroll
    for (int o = 16; o; o >>= 1) v = fmaxf(v, __shfl_xor_sync(0xFFFFFFFFu, v, o));
    return v;
}
__device__ __forceinline__ float warp_sum(float v) {
    #pragma unroll
    for (int o = 16; o; o >>= 1) v += __shfl_xor_sync(0xFFFFFFFFu, v, o);
    return v;
}

// ---------------- pass A softmax ----------------
__global__ __launch_bounds__(256) void k_softmaxA() {
    int gw = (blockIdx.x * blockDim.x + threadIdx.x) >> 5;
    if (gw >= NN) return;
    int lane = threadIdx.x & 31;
    int s = g_rowptr[gw], e = g_rowptr[gw + 1];
    float m0 = -1e30f, m1 = -1e30f, m2 = -1e30f, m3 = -1e30f;
    for (int j = s + lane; j < e; j += 32) {
        float4 sc = ((const float4*)g_scores)[j];
        m0 = fmaxf(m0, sc.x); m1 = fmaxf(m1, sc.y);
        m2 = fmaxf(m2, sc.z); m3 = fmaxf(m3, sc.w);
    }
    m0 = warp_max(m0); m1 = warp_max(m1); m2 = warp_max(m2); m3 = warp_max(m3);
    float t0 = 0.f, t1 = 0.f, t2 = 0.f, t3 = 0.f;
    for (int j = s + lane; j < e; j += 32) {
        float4 sc = ((const float4*)g_scores)[j];
        t0 += expf(sc.x - m0); t1 += expf(sc.y - m1);
        t2 += expf(sc.z - m2); t3 += expf(sc.w - m3);
    }
    t0 = warp_sum(t0) + 1e-16f; t1 = warp_sum(t1) + 1e-16f;
    t2 = warp_sum(t2) + 1e-16f; t3 = warp_sum(t3) + 1e-16f;
    for (int j = s + lane; j < e; j += 32) {
        float4 sc = ((const float4*)g_scores)[j];
        g_meanatt[j] = 0.25f * (expf(sc.x - m0) / t0 + expf(sc.y - m1) / t1 +
                                expf(sc.z - m2) / t2 + expf(sc.w - m3) / t3);
    }
}

// ---------------- exact radix select (rank 79999) + successor ----------------
__global__ void k_sel_init(unsigned rank) {
    int t = threadIdx.x;
    g_hist[t] = 0;
    if (t == 0) {
        g_selShift = 24;
        g_selPrefix = 0;
        g_selMask = 0;
        g_selRank = rank;
        g_cntLE = 0;
        g_minGt = 0xFFFFFFFFu;
    }
}

__global__ void k_sel_hist() {
    __shared__ unsigned sh[256];
    int t = threadIdx.x;
    sh[t] = 0;
    __syncthreads();
    int shf = g_selShift;
    unsigned pre = g_selPrefix, msk = g_selMask;
    for (int e = blockIdx.x * blockDim.x + t; e < EE; e += gridDim.x * blockDim.x) {
        unsigned u = __float_as_uint(g_meanatt[e]);
        if ((u & msk) == pre) atomicAdd(&sh[(u >> shf) & 255], 1u);
    }
    __syncthreads();
    if (sh[t]) atomicAdd(&g_hist[t], sh[t]);
}

__global__ void k_sel_pick(int slot) {
    unsigned rank = g_selRank;
    unsigned cum = 0;
    int chosen = 255;
    int shf = g_selShift;
    for (int b = 0; b < 256; b++) {
        unsigned h = g_hist[b];
        if (rank < cum + h) { chosen = b; break; }
        cum += h;
    }
    g_selRank = rank - cum;
    g_selPrefix |= ((unsigned)chosen) << shf;
    g_selMask |= 0xFFu << shf;
    g_selShift = shf - 8;
    if (shf == 0) g_selResult[slot] = g_selPrefix;
    for (int b = 0; b < 256; b++) g_hist[b] = 0;
}

// count elements <= v0 and min element > v0 (all meanatt > 0 => uint order)
__global__ __launch_bounds__(256) void k_succ() {
    __shared__ unsigned shCnt;
    __shared__ unsigned shMin;
    if (threadIdx.x == 0) { shCnt = 0; shMin = 0xFFFFFFFFu; }
    __syncthreads();
    unsigned v0 = g_selResult[0];
    unsigned cnt = 0;
    unsigned mn = 0xFFFFFFFFu;
    for (int e = blockIdx.x * blockDim.x + threadIdx.x; e < EE;
         e += gridDim.x * blockDim.x) {
        unsigned u = __float_as_uint(g_meanatt[e]);
        if (u <= v0) cnt++;
        else mn = min(mn, u);
    }
    #pragma unroll
    for (int o = 16; o; o >>= 1) {
        cnt += __shfl_xor_sync(0xFFFFFFFFu, cnt, o);
        mn = min(mn, __shfl_xor_sync(0xFFFFFFFFu, mn, o));
    }
    if ((threadIdx.x & 31) == 0) {
        atomicAdd(&shCnt, cnt);
        atomicMin(&shMin, mn);
    }
    __syncthreads();
    if (threadIdx.x == 0) {
        atomicAdd(&g_cntLE, shCnt);
        atomicMin(&g_minGt, shMin);
    }
}

__global__ void k_threshold() {
    float v0 = __uint_as_float(g_selResult[0]);          // v[79999]
    float v1 = (g_cntLE >= 80001u) ? v0
             : __uint_as_float(g_minGt);                 // v[80000]
    g_thr = v0 * 0.046875f + v1 * 0.953125f;
}

// ---------------- pass B masked softmax ----------------
__global__ __launch_bounds__(256) void k_softmaxB() {
    int gw = (blockIdx.x * blockDim.x + threadIdx.x) >> 5;
    if (gw >= NN) return;
    int lane = threadIdx.x & 31;
    int s = g_rowptr[gw], e = g_rowptr[gw + 1];
    float thr = g_thr;
    float m0 = -1e30f, m1 = -1e30f, m2 = -1e30f, m3 = -1e30f;
    for (int j = s + lane; j < e; j += 32) {
        if (g_meanatt[j] > thr) {
            float4 sc = ((const float4*)g_scores)[j];
            m0 = fmaxf(m0, sc.x); m1 = fmaxf(m1, sc.y);
            m2 = fmaxf(m2, sc.z); m3 = fmaxf(m3, sc.w);
        }
    }
    m0 = warp_max(m0); m1 = warp_max(m1); m2 = warp_max(m2); m3 = warp_max(m3);
    float t0 = 0.f, t1 = 0.f, t2 = 0.f, t3 = 0.f;
    for (int j = s + lane; j < e; j += 32) {
        if (g_meanatt[j] > thr) {
            float4 sc = ((const float4*)g_scores)[j];
            t0 += expf(sc.x - m0); t1 += expf(sc.y - m1);
            t2 += expf(sc.z - m2); t3 += expf(sc.w - m3);
        }
    }
    t0 = warp_sum(t0) + 1e-16f; t1 = warp_sum(t1) + 1e-16f;
    t2 = warp_sum(t2) + 1e-16f; t3 = warp_sum(t3) + 1e-16f;
    for (int j = s + lane; j < e; j += 32) {
        float wv = 0.f;
        if (g_meanatt[j] > thr) {
            float4 sc = ((const float4*)g_scores)[j];
            wv = 0.25f * (expf(sc.x - m0) / t0 + expf(sc.y - m1) / t1 +
                          expf(sc.z - m2) / t2 + expf(sc.w - m3) / t3);
        }
        g_w[j] = wv;
    }
}

// ---------------- RK4 ----------------
__global__ void k_copy(const float* __restrict__ src) {
    int i = blockIdx.x * blockDim.x + threadIdx.x;
    if (i < NN * 32) {
        float2 v = ((const float2*)src)[i];
        ((float2*)g_yv)[i] = v;
        g_yvh[i] = __float22half2_rn(v);
    }
}

// One RK4 stage. Gathers fp16 mirror (half traffic), fp32 everywhere else.
// lane owns elements (2*lane, 2*lane+1) of the 64-dim row.
__global__ __launch_bounds__(256) void k_spmv(const __half2* __restrict__ yin_h,
                                              const float* __restrict__ yin_f,
                                              const float* __restrict__ base,
                                              float* __restrict__ nxt,
                                              __half2* __restrict__ nxt_h,
                                              float coefNext,
                                              float accW, int accSet,
                                              int finalMode,
                                              float* __restrict__ fout,
                                              float dt6) {
    int gw = (blockIdx.x * blockDim.x + threadIdx.x) >> 5;
    if (gw >= NN) return;
    int lane = threadIdx.x & 31;
    int s = g_rowptr[gw], e = g_rowptr[gw + 1];
    float a0 = 0.f, a1 = 0.f;
    for (int bj = s; bj < e; bj += 32) {
        int idx = bj + lane;
        float wv = 0.f;
        int cv = 0;
        if (idx < e) { wv = g_w[idx]; cv = g_cols[idx]; }
        int kmax = e - bj;
        if (kmax > 32) kmax = 32;
        for (int k = 0; k < kmax; k++) {
            float wk = __shfl_sync(0xFFFFFFFFu, wv, k);
            int   ck = __shfl_sync(0xFFFFFFFFu, cv, k);
            if (wk != 0.f) {
                __half2 h = yin_h[(size_t)ck * 32 + lane];
                float2 fv = __half22float2(h);
                a0 = fmaf(wk, fv.x, a0);
                a1 = fmaf(wk, fv.y, a1);
            }
        }
    }
    size_t idx2 = (size_t)gw * 32 + lane;
    float2 yb = ((const float2*)yin_f)[idx2];
    float f0 = a0 - yb.x;
    float f1 = a1 - yb.y;
    float2 bb = ((const float2*)base)[idx2];
    if (finalMode) {
        float2 ac = ((const float2*)g_acc)[idx2];
        float2 r;
        r.x = bb.x + dt6 * (ac.x + f0);
        r.y = bb.y + dt6 * (ac.y + f1);
        ((float2*)fout)[idx2] = r;
        if (nxt_h) nxt_h[idx2] = __float22half2_rn(r);
    } else {
        float2 r;
        r.x = bb.x + coefNext * f0;
        r.y = bb.y + coefNext * f1;
        ((float2*)nxt)[idx2] = r;
        nxt_h[idx2] = __float22half2_rn(r);
        float2 ac;
        if (accSet) {
            ac.x = accW * f0;
            ac.y = accW * f1;
        } else {
            ac = ((const float2*)g_acc)[idx2];
            ac.x += accW * f0;
            ac.y += accW * f1;
        }
        ((float2*)g_acc)[idx2] = ac;
    }
}

// ---------------- host launch ----------------
static float*   s_yv   = nullptr;
static float*   s_stA  = nullptr;
static float*   s_stB  = nullptr;
static __half2* s_yvh  = nullptr;
static __half2* s_stAh = nullptr;
static __half2* s_stBh = nullptr;

static void resolve_symbols() {
    if (!s_yv) {
        cudaGetSymbolAddress((void**)&s_yv,   g_yv);
        cudaGetSymbolAddress((void**)&s_stA,  g_stA);
        cudaGetSymbolAddress((void**)&s_stB,  g_stB);
        cudaGetSymbolAddress((void**)&s_yvh,  g_yvh);
        cudaGetSymbolAddress((void**)&s_stAh, g_stAh);
        cudaGetSymbolAddress((void**)&s_stBh, g_stBh);
    }
}

extern "C" void kernel_launch(void* const* d_in, const int* in_sizes, int n_in,
                              void* d_out, int out_size) {
    (void)out_size;
    resolve_symbols();

    const float* x = nullptr;
    const void*  ei = nullptr;
    const float* Wq = nullptr;
    const float* Wk = nullptr;
    for (int i = 0; i < n_in; i++) {
        if (in_sizes[i] == 2 * EE) ei = d_in[i];
        else if (in_sizes[i] == NN * DD) x = (const float*)d_in[i];
        else if (in_sizes[i] == DD * DD) {
            if (!Wq) Wq = (const float*)d_in[i];
            else     Wk = (const float*)d_in[i];
        }
    }
    float* out = (float*)d_out;

    k_detect<<<1, 1024>>>((const int*)ei);
    k_zero_counts<<<(NN + 255) / 256, 256>>>();
    k_count<<<(EE + 255) / 256, 256>>>(ei);
    k_scan1<<<SCAN_NB, SCAN_BS>>>();
    k_scan2<<<1, 128>>>();
    k_scan3<<<SCAN_NB, SCAN_BS>>>();
    k_scatter<<<(EE + 255) / 256, 256>>>(ei);

    k_gemm<<<NN / 4, 256>>>(x, Wq, Wk);
    k_scores<<<(EE + 255) / 256, 256>>>();
    k_softmaxA<<<(NN + 7) / 8, 256>>>();

    // single radix select (rank 79999) + successor pass for rank 80000
    k_sel_init<<<1, 256>>>(79999u);
    for (int p = 0; p < 4; p++) {
        k_sel_hist<<<1024, 256>>>();
        k_sel_pick<<<1, 1>>>(0);
    }
    k_succ<<<1024, 256>>>();
    k_threshold<<<1, 1>>>();

    k_softmaxB<<<(NN + 7) / 8, 256>>>();

    const float dt   = 0.25f;
    const float half = 0.125f;
    const float dt6  = 0.25f / 6.0f;

    k_copy<<<(NN * 32 + 255) / 256, 256>>>(x);

    int grid = (NN * 32 + 255) / 256;
    for (int step = 0; step < 4; step++) {
        // stage 1: f(y)      -> stA = y + dt/2 f ; acc  = f
        k_spmv<<<grid, 256>>>(s_yvh,  s_yv, s_yv, s_stA, s_stAh, half, 1.0f, 1, 0, nullptr, dt6);
        // stage 2: f(stA)    -> stB = y + dt/2 f ; acc += 2f
        k_spmv<<<grid, 256>>>(s_stAh, s_stA, s_yv, s_stB, s_stBh, half, 2.0f, 0, 0, nullptr, dt6);
        // stage 3: f(stB)    -> stA = y + dt f   ; acc += 2f
        k_spmv<<<grid, 256>>>(s_stBh, s_stB, s_yv, s_stA, s_stAh, dt,   2.0f, 0, 0, nullptr, dt6);
        // stage 4: f(stA)    -> ynew = y + dt/6 (acc + f)
        float* finalDst = (step == 3) ? out : s_yv;
        __half2* finalH = (step == 3) ? nullptr : s_yvh;
        k_spmv<<<grid, 256>>>(s_stAh, s_stA, s_yv, nullptr, finalH, 0.f, 0.f, 0, 1, finalDst, dt6);
    }
}

// round 4
// speedup vs baseline: 1.0490x; 1.0490x over previous
#include <cuda_runtime.h>
#include <cuda_fp16.h>
#include <stdint.h>

#define NN 100000
#define EE 1600000
#define DD 64

#define SCAN_BS 1024
#define SCAN_NB ((NN + SCAN_BS - 1) / SCAN_BS)   // 98

// ---------------- device scratch (static; no allocation) ----------------
__device__ int   g_flag64;
__device__ int   g_deg[NN];
__device__ int   g_fill[NN];
__device__ int   g_rowptr[NN + 1];
__device__ int   g_blocksums[128];
__device__ int   g_rows[EE];
__device__ int   g_cols[EE];
__device__ float g_q[NN * DD];
__device__ float g_k[NN * DD];
__device__ float g_scores[EE * 4];
__device__ float g_meanatt[EE];
__device__ float g_w[EE];
__device__ float g_yv[NN * DD];
__device__ float g_stA[NN * DD];
__device__ float g_stB[NN * DD];
__device__ float g_acc[NN * DD];
__device__ __half2 g_yvh[NN * 32];
__device__ __half2 g_stAh[NN * 32];
__device__ __half2 g_stBh[NN * 32];
__device__ unsigned g_hist[256];
__device__ unsigned g_selPrefix;
__device__ unsigned g_selMask;
__device__ int      g_selShift;
__device__ unsigned g_selRank;
__device__ unsigned g_selResult[2];
__device__ unsigned g_cntLE;
__device__ unsigned g_minGt;
__device__ float    g_thr;

// ---------------- dtype detection ----------------
__global__ void k_detect(const int* ei32) {
    int t = threadIdx.x;
    int v = ei32[2 * t + 1];
    int any = __syncthreads_or(v != 0);
    if (t == 0) g_flag64 = (any == 0) ? 1 : 0;
}

__device__ __forceinline__ void load_edge(const void* ei, int e, int& r, int& c) {
    if (g_flag64) {
        const long long* p = (const long long*)ei;
        r = (int)p[e];
        c = (int)p[EE + e];
    } else {
        const int* p = (const int*)ei;
        r = p[e];
        c = p[EE + e];
    }
}

// ---------------- init / CSR build ----------------
__global__ void k_zero_counts() {
    int i = blockIdx.x * blockDim.x + threadIdx.x;
    if (i < NN) { g_deg[i] = 0; g_fill[i] = 0; }
}

__global__ void k_count(const void* ei) {
    int e = blockIdx.x * blockDim.x + threadIdx.x;
    if (e >= EE) return;
    int r, c;
    load_edge(ei, e, r, c);
    atomicAdd(&g_deg[r], 1);
}

__global__ void k_scan1() {
    __shared__ int sh[SCAN_BS];
    int t = threadIdx.x;
    int i = blockIdx.x * SCAN_BS + t;
    int v = (i < NN) ? g_deg[i] : 0;
    sh[t] = v;
    __syncthreads();
    for (int off = 1; off < SCAN_BS; off <<= 1) {
        int x = (t >= off) ? sh[t - off] : 0;
        __syncthreads();
        if (t >= off) sh[t] += x;
        __syncthreads();
    }
    if (i < NN) g_rowptr[i] = sh[t] - v;
    if (t == SCAN_BS - 1) g_blocksums[blockIdx.x] = sh[t];
}

__global__ void k_scan2() {
    __shared__ int sh[128];
    int t = threadIdx.x;
    int v = (t < SCAN_NB) ? g_blocksums[t] : 0;
    sh[t] = v;
    __syncthreads();
    for (int off = 1; off < 128; off <<= 1) {
        int x = (t >= off) ? sh[t - off] : 0;
        __syncthreads();
        if (t >= off) sh[t] += x;
        __syncthreads();
    }
    if (t < SCAN_NB) g_blocksums[t] = sh[t] - v;
    if (t == 0) g_rowptr[NN] = EE;
}

__global__ void k_scan3() {
    int i = blockIdx.x * blockDim.x + threadIdx.x;
    if (i < NN) g_rowptr[i] += g_blocksums[i >> 10];
}

__global__ void k_scatter(const void* ei) {
    int e = blockIdx.x * blockDim.x + threadIdx.x;
    if (e >= EE) return;
    int r, c;
    load_edge(ei, e, r, c);
    int pos = g_rowptr[r] + atomicAdd(&g_fill[r], 1);
    g_rows[pos] = r;
    g_cols[pos] = c;
}

// ---------------- q/k GEMM: 16 rows per block ----------------
__global__ __launch_bounds__(256) void k_gemm(const float* __restrict__ x,
                                              const float* __restrict__ Wq,
                                              const float* __restrict__ Wk) {
    __shared__ float sWq[64 * 64];
    __shared__ float sWk[64 * 64];
    __shared__ float sX[16 * 64];
    int tid = threadIdx.x;
    for (int i = tid; i < 4096; i += 256) { sWq[i] = Wq[i]; sWk[i] = Wk[i]; }
    int rbase = blockIdx.x * 16;
    for (int i = tid; i < 1024; i += 256) sX[i] = x[rbase * 64 + i];
    __syncthreads();
    int q = tid >> 6;          // 0..3
    int c = tid & 63;
    float aq[4] = {0.f, 0.f, 0.f, 0.f};
    float ak[4] = {0.f, 0.f, 0.f, 0.f};
    #pragma unroll
    for (int t = 0; t < 64; t++) {
        float wq = sWq[t * 64 + c];
        float wk = sWk[t * 64 + c];
        #pragma unroll
        for (int j = 0; j < 4; j++) {
            float xv = sX[(q + 4 * j) * 64 + t];
            aq[j] = fmaf(xv, wq, aq[j]);
            ak[j] = fmaf(xv, wk, ak[j]);
        }
    }
    #pragma unroll
    for (int j = 0; j < 4; j++) {
        g_q[(rbase + q + 4 * j) * 64 + c] = aq[j];
        g_k[(rbase + q + 4 * j) * 64 + c] = ak[j];
    }
}

// ---------------- per-edge scores ----------------
__global__ void k_scores() {
    int e = blockIdx.x * blockDim.x + threadIdx.x;
    if (e >= EE) return;
    int r = g_rows[e], c = g_cols[e];
    const float4* qa = (const float4*)(g_q + (size_t)r * 64);
    const float4* kb = (const float4*)(g_k + (size_t)c * 64);
    float out[4];
    #pragma unroll
    for (int h = 0; h < 4; h++) {
        float acc = 0.f;
        #pragma unroll
        for (int t = 0; t < 4; t++) {
            float4 a = qa[h * 4 + t];
            float4 b = kb[h * 4 + t];
            acc += a.x * b.x + a.y * b.y + a.z * b.z + a.w * b.w;
        }
        out[h] = acc * 0.25f;
    }
    ((float4*)g_scores)[e] = make_float4(out[0], out[1], out[2], out[3]);
}

__device__ __forceinline__ float warp_max(float v) {
    #pragma unroll
    for (int o = 16; o; o >>= 1) v = fmaxf(v, __shfl_xor_sync(0xFFFFFFFFu, v, o));
    return v;
}
__device__ __forceinline__ float warp_sum(float v) {
    #pragma unroll
    for (int o = 16; o; o >>= 1) v += __shfl_xor_sync(0xFFFFFFFFu, v, o);
    return v;
}

// ---------------- pass A softmax ----------------
__global__ __launch_bounds__(256) void k_softmaxA() {
    int gw = (blockIdx.x * blockDim.x + threadIdx.x) >> 5;
    if (gw >= NN) return;
    int lane = threadIdx.x & 31;
    int s = g_rowptr[gw], e = g_rowptr[gw + 1];
    float m0 = -1e30f, m1 = -1e30f, m2 = -1e30f, m3 = -1e30f;
    for (int j = s + lane; j < e; j += 32) {
        float4 sc = ((const float4*)g_scores)[j];
        m0 = fmaxf(m0, sc.x); m1 = fmaxf(m1, sc.y);
        m2 = fmaxf(m2, sc.z); m3 = fmaxf(m3, sc.w);
    }
    m0 = warp_max(m0); m1 = warp_max(m1); m2 = warp_max(m2); m3 = warp_max(m3);
    float t0 = 0.f, t1 = 0.f, t2 = 0.f, t3 = 0.f;
    for (int j = s + lane; j < e; j += 32) {
        float4 sc = ((const float4*)g_scores)[j];
        t0 += expf(sc.x - m0); t1 += expf(sc.y - m1);
        t2 += expf(sc.z - m2); t3 += expf(sc.w - m3);
    }
    t0 = warp_sum(t0) + 1e-16f; t1 = warp_sum(t1) + 1e-16f;
    t2 = warp_sum(t2) + 1e-16f; t3 = warp_sum(t3) + 1e-16f;
    for (int j = s + lane; j < e; j += 32) {
        float4 sc = ((const float4*)g_scores)[j];
        g_meanatt[j] = 0.25f * (expf(sc.x - m0) / t0 + expf(sc.y - m1) / t1 +
                                expf(sc.z - m2) / t2 + expf(sc.w - m3) / t3);
    }
}

// ---------------- exact radix select (rank 79999) + successor ----------------
__global__ void k_sel_init(unsigned rank) {
    int t = threadIdx.x;
    g_hist[t] = 0;
    if (t == 0) {
        g_selShift = 24;
        g_selPrefix = 0;
        g_selMask = 0;
        g_selRank = rank;
        g_cntLE = 0;
        g_minGt = 0xFFFFFFFFu;
    }
}

__global__ void k_sel_hist() {
    __shared__ unsigned sh[256];
    int t = threadIdx.x;
    sh[t] = 0;
    __syncthreads();
    int shf = g_selShift;
    unsigned pre = g_selPrefix, msk = g_selMask;
    for (int e = blockIdx.x * blockDim.x + t; e < EE; e += gridDim.x * blockDim.x) {
        unsigned u = __float_as_uint(g_meanatt[e]);
        if ((u & msk) == pre) atomicAdd(&sh[(u >> shf) & 255], 1u);
    }
    __syncthreads();
    if (sh[t]) atomicAdd(&g_hist[t], sh[t]);
}

__global__ void k_sel_pick(int slot) {
    unsigned rank = g_selRank;
    unsigned cum = 0;
    int chosen = 255;
    int shf = g_selShift;
    for (int b = 0; b < 256; b++) {
        unsigned h = g_hist[b];
        if (rank < cum + h) { chosen = b; break; }
        cum += h;
    }
    g_selRank = rank - cum;
    g_selPrefix |= ((unsigned)chosen) << shf;
    g_selMask |= 0xFFu << shf;
    g_selShift = shf - 8;
    if (shf == 0) g_selResult[slot] = g_selPrefix;
    for (int b = 0; b < 256; b++) g_hist[b] = 0;
}

// count elements <= v0 and min element > v0 (all meanatt > 0 => uint order)
__global__ __launch_bounds__(256) void k_succ() {
    __shared__ unsigned shCnt;
    __shared__ unsigned shMin;
    if (threadIdx.x == 0) { shCnt = 0; shMin = 0xFFFFFFFFu; }
    __syncthreads();
    unsigned v0 = g_selResult[0];
    unsigned cnt = 0;
    unsigned mn = 0xFFFFFFFFu;
    for (int e = blockIdx.x * blockDim.x + threadIdx.x; e < EE;
         e += gridDim.x * blockDim.x) {
        unsigned u = __float_as_uint(g_meanatt[e]);
        if (u <= v0) cnt++;
        else mn = min(mn, u);
    }
    #pragma unroll
    for (int o = 16; o; o >>= 1) {
        cnt += __shfl_xor_sync(0xFFFFFFFFu, cnt, o);
        mn = min(mn, __shfl_xor_sync(0xFFFFFFFFu, mn, o));
    }
    if ((threadIdx.x & 31) == 0) {
        atomicAdd(&shCnt, cnt);
        atomicMin(&shMin, mn);
    }
    __syncthreads();
    if (threadIdx.x == 0) {
        atomicAdd(&g_cntLE, shCnt);
        atomicMin(&g_minGt, shMin);
    }
}

__global__ void k_threshold() {
    float v0 = __uint_as_float(g_selResult[0]);          // v[79999]
    float v1 = (g_cntLE >= 80001u) ? v0
             : __uint_as_float(g_minGt);                 // v[80000]
    g_thr = v0 * 0.046875f + v1 * 0.953125f;
}

// ---------------- pass B masked softmax ----------------
__global__ __launch_bounds__(256) void k_softmaxB() {
    int gw = (blockIdx.x * blockDim.x + threadIdx.x) >> 5;
    if (gw >= NN) return;
    int lane = threadIdx.x & 31;
    int s = g_rowptr[gw], e = g_rowptr[gw + 1];
    float thr = g_thr;
    float m0 = -1e30f, m1 = -1e30f, m2 = -1e30f, m3 = -1e30f;
    for (int j = s + lane; j < e; j += 32) {
        if (g_meanatt[j] > thr) {
            float4 sc = ((const float4*)g_scores)[j];
            m0 = fmaxf(m0, sc.x); m1 = fmaxf(m1, sc.y);
            m2 = fmaxf(m2, sc.z); m3 = fmaxf(m3, sc.w);
        }
    }
    m0 = warp_max(m0); m1 = warp_max(m1); m2 = warp_max(m2); m3 = warp_max(m3);
    float t0 = 0.f, t1 = 0.f, t2 = 0.f, t3 = 0.f;
    for (int j = s + lane; j < e; j += 32) {
        if (g_meanatt[j] > thr) {
            float4 sc = ((const float4*)g_scores)[j];
            t0 += expf(sc.x - m0); t1 += expf(sc.y - m1);
            t2 += expf(sc.z - m2); t3 += expf(sc.w - m3);
        }
    }
    t0 = warp_sum(t0) + 1e-16f; t1 = warp_sum(t1) + 1e-16f;
    t2 = warp_sum(t2) + 1e-16f; t3 = warp_sum(t3) + 1e-16f;
    for (int j = s + lane; j < e; j += 32) {
        float wv = 0.f;
        if (g_meanatt[j] > thr) {
            float4 sc = ((const float4*)g_scores)[j];
            wv = 0.25f * (expf(sc.x - m0) / t0 + expf(sc.y - m1) / t1 +
                          expf(sc.z - m2) / t2 + expf(sc.w - m3) / t3);
        }
        g_w[j] = wv;
    }
}

// ---------------- RK4 ----------------
__global__ void k_copy(const float* __restrict__ src) {
    int i = blockIdx.x * blockDim.x + threadIdx.x;
    if (i < NN * 32) {
        float2 v = ((const float2*)src)[i];
        ((float2*)g_yv)[i] = v;
        g_yvh[i] = __float22half2_rn(v);
    }
}

// One RK4 stage. Gathers fp16 mirror, fp32 everywhere else.
__global__ __launch_bounds__(256) void k_spmv(const __half2* __restrict__ yin_h,
                                              const float* __restrict__ yin_f,
                                              const float* __restrict__ base,
                                              float* __restrict__ nxt,
                                              __half2* __restrict__ nxt_h,
                                              float coefNext,
                                              float accW, int accSet,
                                              int finalMode,
                                              float* __restrict__ fout,
                                              float dt6) {
    int gw = (blockIdx.x * blockDim.x + threadIdx.x) >> 5;
    if (gw >= NN) return;
    int lane = threadIdx.x & 31;
    int s = g_rowptr[gw], e = g_rowptr[gw + 1];
    float a0 = 0.f, a1 = 0.f;
    for (int bj = s; bj < e; bj += 32) {
        int idx = bj + lane;
        float wv = 0.f;
        int cv = 0;
        if (idx < e) { wv = g_w[idx]; cv = g_cols[idx]; }
        int kmax = e - bj;
        if (kmax > 32) kmax = 32;
        for (int k = 0; k < kmax; k++) {
            float wk = __shfl_sync(0xFFFFFFFFu, wv, k);
            int   ck = __shfl_sync(0xFFFFFFFFu, cv, k);
            if (wk != 0.f) {
                __half2 h = yin_h[(size_t)ck * 32 + lane];
                float2 fv = __half22float2(h);
                a0 = fmaf(wk, fv.x, a0);
                a1 = fmaf(wk, fv.y, a1);
            }
        }
    }
    size_t idx2 = (size_t)gw * 32 + lane;
    float2 yb = ((const float2*)yin_f)[idx2];
    float f0 = a0 - yb.x;
    float f1 = a1 - yb.y;
    float2 bb = ((const float2*)base)[idx2];
    if (finalMode) {
        float2 ac = ((const float2*)g_acc)[idx2];
        float2 r;
        r.x = bb.x + dt6 * (ac.x + f0);
        r.y = bb.y + dt6 * (ac.y + f1);
        ((float2*)fout)[idx2] = r;
        if (nxt_h) nxt_h[idx2] = __float22half2_rn(r);
    } else {
        float2 r;
        r.x = bb.x + coefNext * f0;
        r.y = bb.y + coefNext * f1;
        ((float2*)nxt)[idx2] = r;
        nxt_h[idx2] = __float22half2_rn(r);
        float2 ac;
        if (accSet) {
            ac.x = accW * f0;
            ac.y = accW * f1;
        } else {
            ac = ((const float2*)g_acc)[idx2];
            ac.x += accW * f0;
            ac.y += accW * f1;
        }
        ((float2*)g_acc)[idx2] = ac;
    }
}

// ---------------- host launch ----------------
static float*   s_yv   = nullptr;
static float*   s_stA  = nullptr;
static float*   s_stB  = nullptr;
static __half2* s_yvh  = nullptr;
static __half2* s_stAh = nullptr;
static __half2* s_stBh = nullptr;

static void resolve_symbols() {
    if (!s_yv) {
        cudaGetSymbolAddress((void**)&s_yv,   g_yv);
        cudaGetSymbolAddress((void**)&s_stA,  g_stA);
        cudaGetSymbolAddress((void**)&s_stB,  g_stB);
        cudaGetSymbolAddress((void**)&s_yvh,  g_yvh);
        cudaGetSymbolAddress((void**)&s_stAh, g_stAh);
        cudaGetSymbolAddress((void**)&s_stBh, g_stBh);
    }
}

extern "C" void kernel_launch(void* const* d_in, const int* in_sizes, int n_in,
                              void* d_out, int out_size) {
    (void)out_size;
    resolve_symbols();

    const float* x = nullptr;
    const void*  ei = nullptr;
    const float* Wq = nullptr;
    const float* Wk = nullptr;
    for (int i = 0; i < n_in; i++) {
        if (in_sizes[i] == 2 * EE) ei = d_in[i];
        else if (in_sizes[i] == NN * DD) x = (const float*)d_in[i];
        else if (in_sizes[i] == DD * DD) {
            if (!Wq) Wq = (const float*)d_in[i];
            else     Wk = (const float*)d_in[i];
        }
    }
    float* out = (float*)d_out;

    int grid = (NN * 32 + 255) / 256;

    k_detect<<<1, 1024>>>((const int*)ei);          // our launch 0
    k_zero_counts<<<(NN + 255) / 256, 256>>>();     // 1
    k_count<<<(EE + 255) / 256, 256>>>(ei);         // 2

    // PROFILING TAP (our launch 3 — the slot ncu's -s 5 profiles).
    // At this point g_rowptr/g_cols/g_w/g_yv still hold the previous
    // invocation's final (bit-identical) values, so this executes a real
    // stage-1 SpMV workload; on the very first call rowptr is zeroed BSS so
    // it no-ops. Everything it writes is fully overwritten by the real
    // stage 1 below. Costs one SpMV; yields dur-delta + ncu profile of it.
    k_spmv<<<grid, 256>>>(s_yvh, s_yv, s_yv, s_stA, s_stAh,
                          0.125f, 1.0f, 1, 0, nullptr, 0.25f / 6.0f);

    k_scan1<<<SCAN_NB, SCAN_BS>>>();
    k_scan2<<<1, 128>>>();
    k_scan3<<<SCAN_NB, SCAN_BS>>>();
    k_scatter<<<(EE + 255) / 256, 256>>>(ei);

    k_gemm<<<NN / 16, 256>>>(x, Wq, Wk);
    k_scores<<<(EE + 255) / 256, 256>>>();
    k_softmaxA<<<(NN + 7) / 8, 256>>>();

    k_sel_init<<<1, 256>>>(79999u);
    for (int p = 0; p < 4; p++) {
        k_sel_hist<<<1024, 256>>>();
        k_sel_pick<<<1, 1>>>(0);
    }
    k_succ<<<1024, 256>>>();
    k_threshold<<<1, 1>>>();

    k_softmaxB<<<(NN + 7) / 8, 256>>>();

    const float dt   = 0.25f;
    const float half = 0.125f;
    const float dt6  = 0.25f / 6.0f;

    k_copy<<<(NN * 32 + 255) / 256, 256>>>(x);

    for (int step = 0; step < 4; step++) {
        k_spmv<<<grid, 256>>>(s_yvh,  s_yv, s_yv, s_stA, s_stAh, half, 1.0f, 1, 0, nullptr, dt6);
        k_spmv<<<grid, 256>>>(s_stAh, s_stA, s_yv, s_stB, s_stBh, half, 2.0f, 0, 0, nullptr, dt6);
        k_spmv<<<grid, 256>>>(s_stBh, s_stB, s_yv, s_stA, s_stAh, dt,   2.0f, 0, 0, nullptr, dt6);
        float* finalDst = (step == 3) ? out : s_yv;
        __half2* finalH = (step == 3) ? nullptr : s_yvh;
        k_spmv<<<grid, 256>>>(s_stAh, s_stA, s_yv, nullptr, finalH, 0.f, 0.f, 0, 1, finalDst, dt6);
    }
}